// round 16
// baseline (speedup 1.0000x reference)
#include <cuda_runtime.h>

// LIF neuron scan, round 15: r9 skeleton with fully warp-independent pipelines.
//
// Bench (deterministic per config) ranks r9 (3-ring, dist-1) best at 69.8us;
// dist-2/4-ring consistently 75.8 despite better ncu numbers -> closed.
// Remaining r9 cost: two CTA-wide __syncthreads + single-thread bulk_wait
// per iteration convoy all 4 warps. But each warp's 32 rows are a contiguous
// 12.8 KB slice of the tile, so the whole pipeline (cp.async load, compute,
// bulk store) decomposes per-warp: __syncwarp only, per-warp bulk groups
// (lane 0 issues/waits its own), warps free-run out of phase.

#define T_STEPS   100
#define T_VEC     (T_STEPS / 4)          // 25 float4 per row
#define ROWS_CTA  128
#define TILE_V4   (ROWS_CTA * T_VEC)     // 3200 float4 = 50 KB
#define WSLICE_V4 (32 * T_VEC)           // 800 float4 = 12.8 KB per warp
#define WSLICE_BYTES (WSLICE_V4 * 16)
#define GRID_P    148                    // 1 persistent CTA per SM

__device__ __forceinline__ void cp_async16(float4* smem_dst, const float4* gmem_src) {
    unsigned saddr = (unsigned)__cvta_generic_to_shared(smem_dst);
    asm volatile("cp.async.cg.shared.global [%0], [%1], 16;\n" :: "r"(saddr), "l"(gmem_src));
}
__device__ __forceinline__ void cp_commit() {
    asm volatile("cp.async.commit_group;\n");
}
template <int N>
__device__ __forceinline__ void cp_wait() {
    asm volatile("cp.async.wait_group %0;\n" :: "n"(N));
}

__device__ __forceinline__ void bulk_store(float4* gmem_dst, const float4* smem_src, unsigned bytes) {
    unsigned saddr = (unsigned)__cvta_generic_to_shared(smem_src);
    asm volatile("cp.async.bulk.global.shared::cta.bulk_group [%0], [%1], %2;\n"
                 :: "l"(gmem_dst), "r"(saddr), "r"(bytes) : "memory");
}
__device__ __forceinline__ void bulk_commit() {
    asm volatile("cp.async.bulk.commit_group;\n");
}
template <int N>
__device__ __forceinline__ void bulk_wait() {
    asm volatile("cp.async.bulk.wait_group %0;\n" :: "n"(N) : "memory");
}
__device__ __forceinline__ void fence_async_proxy() {
    asm volatile("fence.proxy.async.shared::cta;\n" ::: "memory");
}

__global__ __launch_bounds__(ROWS_CTA, 1) void lif_kernel(const float4* __restrict__ x,
                                                          float4* __restrict__ out,
                                                          int ntiles) {
    extern __shared__ float4 smem[];              // [3 * TILE_V4]

    const int tid    = threadIdx.x;
    const int wid    = tid >> 5;
    const int lane   = tid & 31;
    const int stride = gridDim.x;

    const int tile0 = blockIdx.x;
    if (tile0 >= ntiles) return;

    // This warp's slice offset within any tile/buffer (contiguous 12.8 KB).
    const int woff = wid * WSLICE_V4;

    // Per-warp slice views of the 3-buffer ring.
    float4* wbuf[3] = { smem + woff, smem + TILE_V4 + woff, smem + 2 * TILE_V4 + woff };

    // Prologue: this warp loads its slice of the first tile.
    {
        const float4* src = x + (long long)tile0 * TILE_V4 + woff;
        float4* dst = wbuf[0];
        #pragma unroll
        for (int i = 0; i < T_VEC; ++i)
            cp_async16(&dst[lane + 32 * i], &src[lane + 32 * i]);
        cp_commit();
    }

    int j = 0;
    for (long long tile = tile0; tile < ntiles; tile += stride, ++j) {
        float4* cur = wbuf[j % 3];
        float4* nxt = wbuf[(j + 1) % 3];

        long long next = tile + stride;
        if (next < ntiles) {
            // nxt slice's bulk store (this warp's lane 0, iter j-2) is the
            // oldest of at most 2 outstanding; drain it before overwriting.
            if (lane == 0) bulk_wait<1>();
            __syncwarp();

            // Issue next slice's loads BEFORE waiting on the current ones.
            const float4* src = x + next * TILE_V4 + woff;
            #pragma unroll
            for (int i = 0; i < T_VEC; ++i)
                cp_async16(&nxt[lane + 32 * i], &src[lane + 32 * i]);
            cp_commit();
            cp_wait<1>();       // this thread's current-slice group landed
        } else {
            cp_wait<0>();
        }
        __syncwarp();

        // ---- Compute: serial LIF scan of this thread's row, in place ----
        const float decay = 0.5f;
        const float vth   = 0.5f;
        float v = 0.0f;
        float4* __restrict__ row = cur + lane * T_VEC;

        #pragma unroll
        for (int i = 0; i < T_VEC; ++i) {
            float4 xi = row[i];
            float4 so;

            v = fmaf(v, decay, xi.x);
            so.x = (v > vth) ? 1.0f : 0.0f;
            v = fmaf(so.x, -vth, v);

            v = fmaf(v, decay, xi.y);
            so.y = (v > vth) ? 1.0f : 0.0f;
            v = fmaf(so.y, -vth, v);

            v = fmaf(v, decay, xi.z);
            so.z = (v > vth) ? 1.0f : 0.0f;
            v = fmaf(so.z, -vth, v);

            v = fmaf(v, decay, xi.w);
            so.w = (v > vth) ? 1.0f : 0.0f;
            v = fmaf(so.w, -vth, v);

            row[i] = so;
        }

        // Order this warp's generic smem writes before the async-proxy read,
        // then lane 0 fires the 12.8 KB slice store.
        fence_async_proxy();
        __syncwarp();
        if (lane == 0) {
            bulk_store(out + tile * TILE_V4 + woff, cur, WSLICE_BYTES);
            bulk_commit();
        }
    }

    // Drain this warp's outstanding bulk stores before exit.
    if (lane == 0) bulk_wait<0>();
}

extern "C" void kernel_launch(void* const* d_in, const int* in_sizes, int n_in,
                              void* d_out, int out_size) {
    const float4* x = (const float4*)d_in[0];
    float4* out = (float4*)d_out;

    int n_rows = in_sizes[0] / T_STEPS;          // 524288
    int ntiles = n_rows / ROWS_CTA;              // 4096

    size_t smem_bytes = 3 * (size_t)TILE_V4 * sizeof(float4);   // 150 KB
    static bool attr_set = false;
    if (!attr_set) {
        cudaFuncSetAttribute(lif_kernel, cudaFuncAttributeMaxDynamicSharedMemorySize,
                             (int)smem_bytes);
        attr_set = true;
    }
    int grid = ntiles < GRID_P ? ntiles : GRID_P;
    lif_kernel<<<grid, ROWS_CTA, smem_bytes>>>(x, out, ntiles);
}

// round 17
// speedup vs baseline: 1.1460x; 1.1460x over previous
#include <cuda_runtime.h>

// LIF neuron scan, round 16: r9-exact pipeline + L2 evict_first hints on both
// streaming paths.
//
// Structure search is closed: r9 (3-ring, dist-1, issue-before-wait, CTA-wide
// barriers, 128-row tiles, grid 148) beats every variant tried (dist-2 ring,
// per-warp pipelines, barrier reorder, FSEL step) on the bench. Remaining
// lever: both GMEM streams are touch-once but fully allocate in L2. Mark
// loads (cp.async.cg.L2::cache_hint) and bulk stores
// (cp.async.bulk.L2::cache_hint) evict_first so streaming lines don't thrash
// L2 ways, smoothing LTS/DRAM scheduling.

#define T_STEPS   100
#define T_VEC     (T_STEPS / 4)        // 25 float4 per row
#define ROWS_CTA  128
#define TILE_V4   (ROWS_CTA * T_VEC)   // 3200 float4 = 50 KB
#define TILE_BYTES (TILE_V4 * 16)
#define GRID_P    148                  // 1 persistent CTA per SM

__device__ __forceinline__ unsigned long long make_evict_first_policy() {
    unsigned long long pol;
    asm("createpolicy.fractional.L2::evict_first.b64 %0, 1.0;" : "=l"(pol));
    return pol;
}

__device__ __forceinline__ void cp_async16(float4* smem_dst, const float4* gmem_src,
                                           unsigned long long pol) {
    unsigned saddr = (unsigned)__cvta_generic_to_shared(smem_dst);
    asm volatile("cp.async.cg.shared.global.L2::cache_hint [%0], [%1], 16, %2;\n"
                 :: "r"(saddr), "l"(gmem_src), "l"(pol));
}
__device__ __forceinline__ void cp_commit() {
    asm volatile("cp.async.commit_group;\n");
}
template <int N>
__device__ __forceinline__ void cp_wait() {
    asm volatile("cp.async.wait_group %0;\n" :: "n"(N));
}

__device__ __forceinline__ void bulk_store(float4* gmem_dst, const float4* smem_src,
                                           unsigned bytes, unsigned long long pol) {
    unsigned saddr = (unsigned)__cvta_generic_to_shared(smem_src);
    asm volatile("cp.async.bulk.global.shared::cta.bulk_group.L2::cache_hint [%0], [%1], %2, %3;\n"
                 :: "l"(gmem_dst), "r"(saddr), "r"(bytes), "l"(pol) : "memory");
}
__device__ __forceinline__ void bulk_commit() {
    asm volatile("cp.async.bulk.commit_group;\n");
}
template <int N>
__device__ __forceinline__ void bulk_wait() {
    asm volatile("cp.async.bulk.wait_group %0;\n" :: "n"(N) : "memory");
}
__device__ __forceinline__ void fence_async_proxy() {
    asm volatile("fence.proxy.async.shared::cta;\n" ::: "memory");
}

__global__ __launch_bounds__(ROWS_CTA, 1) void lif_kernel(const float4* __restrict__ x,
                                                          float4* __restrict__ out,
                                                          int ntiles) {
    extern __shared__ float4 smem[];              // [3 * TILE_V4]
    float4* bA = smem;                            // ring: cur, next, spare
    float4* bB = smem + TILE_V4;
    float4* bC = smem + 2 * TILE_V4;

    const int tid    = threadIdx.x;
    const int stride = gridDim.x;
    const unsigned long long pol = make_evict_first_policy();

    int tile0 = blockIdx.x;
    if (tile0 >= ntiles) return;

    // Prologue: prefetch first tile into bA.
    {
        const float4* src = x + (long long)tile0 * TILE_V4;
        #pragma unroll
        for (int i = 0; i < T_VEC; ++i)
            cp_async16(&bA[tid + ROWS_CTA * i], &src[tid + ROWS_CTA * i], pol);
        cp_commit();
    }

    for (long long tile = tile0; tile < ntiles; tile += stride) {
        float4* cur = bA;
        float4* nxt = bB;

        long long next = tile + stride;
        if (next < ntiles) {
            // nxt's bulk store was issued 2 iterations ago. Outstanding stores
            // now: {iter-2 (on nxt), iter-1}. wait<1> drains iter-2, leaves
            // iter-1 in flight -> safe to overwrite nxt, store stays async.
            if (tid == 0) bulk_wait<1>();
            __syncthreads();

            // ISSUE next tile's load BEFORE waiting on the current one: the
            // read stream stays non-empty while we stall.
            const float4* src = x + next * TILE_V4;
            #pragma unroll
            for (int i = 0; i < T_VEC; ++i)
                cp_async16(&nxt[tid + ROWS_CTA * i], &src[tid + ROWS_CTA * i], pol);
            cp_commit();
            cp_wait<1>();       // current tile's load group has landed
        } else {
            cp_wait<0>();
        }
        __syncthreads();

        // ---- Compute: serial LIF scan of this thread's row, in place ----
        const float decay = 0.5f;
        const float vth   = 0.5f;
        float v = 0.0f;
        float4* __restrict__ row = cur + tid * T_VEC;

        #pragma unroll
        for (int i = 0; i < T_VEC; ++i) {
            float4 xi = row[i];
            float4 so;

            v = fmaf(v, decay, xi.x);
            so.x = (v > vth) ? 1.0f : 0.0f;
            v = fmaf(so.x, -vth, v);

            v = fmaf(v, decay, xi.y);
            so.y = (v > vth) ? 1.0f : 0.0f;
            v = fmaf(so.y, -vth, v);

            v = fmaf(v, decay, xi.z);
            so.z = (v > vth) ? 1.0f : 0.0f;
            v = fmaf(so.z, -vth, v);

            v = fmaf(v, decay, xi.w);
            so.w = (v > vth) ? 1.0f : 0.0f;
            v = fmaf(so.w, -vth, v);

            row[i] = so;
        }

        // Order generic smem writes before the async-proxy bulk read, then
        // fire-and-forget the 50 KB tile store.
        fence_async_proxy();
        __syncthreads();
        if (tid == 0) {
            bulk_store(out + tile * TILE_V4, cur, TILE_BYTES, pol);
            bulk_commit();
        }

        // Rotate ring: A<-B (next tile's data), B<-C (free), C<-A (storing).
        float4* t = bA; bA = bB; bB = bC; bC = t;
    }

    // Drain outstanding bulk stores before exit.
    if (tid == 0) bulk_wait<0>();
}

extern "C" void kernel_launch(void* const* d_in, const int* in_sizes, int n_in,
                              void* d_out, int out_size) {
    const float4* x = (const float4*)d_in[0];
    float4* out = (float4*)d_out;

    int n_rows = in_sizes[0] / T_STEPS;          // 524288
    int ntiles = n_rows / ROWS_CTA;              // 4096

    size_t smem_bytes = 3 * (size_t)TILE_V4 * sizeof(float4);   // 150 KB
    static bool attr_set = false;
    if (!attr_set) {
        cudaFuncSetAttribute(lif_kernel, cudaFuncAttributeMaxDynamicSharedMemorySize,
                             (int)smem_bytes);
        attr_set = true;
    }
    int grid = ntiles < GRID_P ? ntiles : GRID_P;
    lif_kernel<<<grid, ROWS_CTA, smem_bytes>>>(x, out, ntiles);
}